// round 2
// baseline (speedup 1.0000x reference)
#include <cuda_runtime.h>
#include <cstdint>
#include <cstddef>

// Problem dims (fixed)
#define BB   32
#define TT   4096
#define DIN  256
#define HH   256
#define G4   1024   // 4*H

// ---------------- scratch (static device arrays; no allocation) ----------------
__device__ float    g_xg[(size_t)BB * TT * G4];   // 512 MB  : x @ Wx + b
__device__ float    g_hseq[(size_t)BB * TT * HH]; // 128 MB  : h_t for all t
__device__ float    g_hstate[BB * HH];            // current h (exchange buffer)
__device__ unsigned g_cnt[16];                    // per-batch-pair sync counters

__global__ void init_kernel() {
    if (threadIdx.x < 16) g_cnt[threadIdx.x] = 0u;
}

// ---------------- generic fp32 GEMM: C[M,N] = A[M,K] @ B[K,N] + bias[N] -------
// BM=128, BN=128, BK=8, 256 threads, 8x8 microtile (split-tile for conflict-free LDS.128)
__global__ void __launch_bounds__(256) sgemm_bias_128(
    const float* __restrict__ A, const float* __restrict__ B,
    const float* __restrict__ bias, float* __restrict__ C,
    int M, int N, int K)
{
    __shared__ __align__(16) float As[8][128];
    __shared__ __align__(16) float Bs[8][128];

    const int tid = threadIdx.x;
    const int bm  = blockIdx.y;
    const int bn  = blockIdx.x;
    const int tx  = tid & 15;    // 0..15
    const int ty  = tid >> 4;    // 0..15

    // load mapping
    const int arow = tid >> 1;         // 0..127
    const int ak   = (tid & 1) * 4;    // 0 or 4
    const int brow = tid >> 5;         // 0..7
    const int bcol = (tid & 31) * 4;   // 0..124

    const float* Aptr = A + (size_t)(bm * 128 + arow) * K + ak;
    const float* Bptr = B + (size_t)brow * N + bn * 128 + bcol;

    float acc[8][8];
#pragma unroll
    for (int i = 0; i < 8; i++)
#pragma unroll
        for (int j = 0; j < 8; j++) acc[i][j] = 0.f;

    for (int k0 = 0; k0 < K; k0 += 8) {
        const float4 va = *(const float4*)(Aptr + k0);
        const float4 vb = *(const float4*)(Bptr + (size_t)k0 * N);
        __syncthreads();
        As[ak + 0][arow] = va.x;
        As[ak + 1][arow] = va.y;
        As[ak + 2][arow] = va.z;
        As[ak + 3][arow] = va.w;
        *(float4*)&Bs[brow][bcol] = vb;
        __syncthreads();

#pragma unroll
        for (int k = 0; k < 8; k++) {
            float a0[4], a1[4], b0v[4], b1v[4];
            *(float4*)a0  = *(const float4*)&As[k][ty * 4];
            *(float4*)a1  = *(const float4*)&As[k][64 + ty * 4];
            *(float4*)b0v = *(const float4*)&Bs[k][tx * 4];
            *(float4*)b1v = *(const float4*)&Bs[k][64 + tx * 4];
#pragma unroll
            for (int i = 0; i < 4; i++) {
#pragma unroll
                for (int j = 0; j < 4; j++) {
                    acc[i][j]         = fmaf(a0[i], b0v[j], acc[i][j]);
                    acc[i][j + 4]     = fmaf(a0[i], b1v[j], acc[i][j + 4]);
                    acc[i + 4][j]     = fmaf(a1[i], b0v[j], acc[i + 4][j]);
                    acc[i + 4][j + 4] = fmaf(a1[i], b1v[j], acc[i + 4][j + 4]);
                }
            }
        }
    }

    // bias values for this thread's 8 columns
    float bvals[8];
#pragma unroll
    for (int j = 0; j < 4; j++) {
        bvals[j]     = bias[bn * 128 + tx * 4 + j];
        bvals[j + 4] = bias[bn * 128 + 64 + tx * 4 + j];
    }

#pragma unroll
    for (int i = 0; i < 8; i++) {
        const int row = bm * 128 + ((i < 4) ? (ty * 4 + i) : (64 + ty * 4 + (i - 4)));
        float4 o0, o1;
        o0.x = acc[i][0] + bvals[0]; o0.y = acc[i][1] + bvals[1];
        o0.z = acc[i][2] + bvals[2]; o0.w = acc[i][3] + bvals[3];
        o1.x = acc[i][4] + bvals[4]; o1.y = acc[i][5] + bvals[5];
        o1.z = acc[i][6] + bvals[6]; o1.w = acc[i][7] + bvals[7];
        *(float4*)&C[(size_t)row * N + bn * 128 + tx * 4]      = o0;
        *(float4*)&C[(size_t)row * N + bn * 128 + 64 + tx * 4] = o1;
    }
}

// ---------------- recurrence kernel ----------------
// Grid: 128 persistent CTAs (all co-resident on 148 SMs, spin-sync safe).
// CTA = (batch pair grp, h-index block j). Owns 2 batches x 128 gate-cols,
// where the 128 cols = 4 gates x 32 h-indices [32j, 32j+32).
// Threads: 256 = 128 cols x 2 K-halves. Wh slice lives in REGISTERS (128 fp32/thread),
// loaded once; per-step SMEM traffic is only the h broadcast.
__global__ void __launch_bounds__(256, 1) lstm_rec(const float* __restrict__ Wh)
{
    const int cta  = blockIdx.x;    // 0..127
    const int grp  = cta >> 3;      // 0..15 (batch pair)
    const int j    = cta & 7;       // h-index block
    const int b0   = grp * 2, b1 = b0 + 1;
    const int tid  = threadIdx.x;
    const int q    = tid & 127;     // col within CTA
    const int kh   = tid >> 7;      // K-half 0/1 (uniform per warp)
    const int gate = q >> 5;
    const int l    = q & 31;
    const int colg = gate * 256 + j * 32 + l;   // column in [0,1024)

    __shared__ __align__(16) float hs0[256];
    __shared__ __align__(16) float hs1[256];
    __shared__ float red0[128], red1[128];
    __shared__ float gsm0[128], gsm1[128];
    __shared__ float csm[2][32];

    // Persistent weight slice in registers: Wh[kh*128 + jj][colg]
    float w[128];
    {
        const float* wp = Wh + (size_t)(kh * 128) * G4 + colg;
#pragma unroll
        for (int jj = 0; jj < 128; jj++) w[jj] = __ldg(&wp[(size_t)jj * G4]);
    }

    hs0[tid] = 0.f;
    hs1[tid] = 0.f;
    if (tid < 64) csm[tid >> 5][tid & 31] = 0.f;
    __syncthreads();

    const float4* h0v = (const float4*)(hs0 + kh * 128);
    const float4* h1v = (const float4*)(hs1 + kh * 128);

    for (int t = 0; t < TT; t++) {
        // xg for this step (only kh==0 threads consume it; load early to overlap)
        float xv0 = 0.f, xv1 = 0.f;
        if (kh == 0) {
            xv0 = __ldg(&g_xg[((size_t)(b0 * TT + t)) * G4 + colg]);
            xv1 = __ldg(&g_xg[((size_t)(b1 * TT + t)) * G4 + colg]);
        }

        // partial dot over this thread's K-half (128 k), 2 batches
        float s00 = 0.f, s01 = 0.f, s10 = 0.f, s11 = 0.f;
#pragma unroll
        for (int j4 = 0; j4 < 32; j4++) {
            const float4 h0 = h0v[j4];
            const float4 h1 = h1v[j4];
            s00 = fmaf(w[4 * j4 + 0], h0.x, s00);
            s01 = fmaf(w[4 * j4 + 1], h0.y, s01);
            s00 = fmaf(w[4 * j4 + 2], h0.z, s00);
            s01 = fmaf(w[4 * j4 + 3], h0.w, s01);
            s10 = fmaf(w[4 * j4 + 0], h1.x, s10);
            s11 = fmaf(w[4 * j4 + 1], h1.y, s11);
            s10 = fmaf(w[4 * j4 + 2], h1.z, s10);
            s11 = fmaf(w[4 * j4 + 3], h1.w, s11);
        }

        if (kh == 1) { red0[q] = s00 + s01; red1[q] = s10 + s11; }
        __syncthreads();
        if (kh == 0) {
            gsm0[q] = s00 + s01 + red0[q] + xv0;   // bias already folded into xg
            gsm1[q] = s10 + s11 + red1[q] + xv1;
        }
        __syncthreads();

        // activations + state update: 64 threads = 2 batches x 32 h-indices
        if (tid < 64) {
            const int bb = tid >> 5, ll = tid & 31;
            const float* gp = bb ? gsm1 : gsm0;
            const float gi = gp[ll];
            const float gf = gp[32 + ll];
            const float gg = gp[64 + ll];
            const float go = gp[96 + ll];
            const float cprev = csm[bb][ll];
            const float si = 1.f / (1.f + __expf(-gi));
            const float sf = 1.f / (1.f + __expf(-gf));
            const float so = 1.f / (1.f + __expf(-go));
            const float tg = 2.f / (1.f + __expf(-2.f * gg)) - 1.f;
            const float cn = sf * cprev + si * tg;
            const float tc = 2.f / (1.f + __expf(-2.f * cn)) - 1.f;
            const float hn = so * tc;
            csm[bb][ll] = cn;
            const int bg   = bb ? b1 : b0;
            const int hidx = j * 32 + ll;
            // L2-visible stores (L1 is not coherent across SMs)
            __stcg(&g_hstate[bg * HH + hidx], hn);
            __stcg(&g_hseq[((size_t)(bg * TT + t)) * HH + hidx], hn);
        }

        if (t + 1 < TT) {
            __threadfence();     // push h stores to L2 before signaling
            __syncthreads();
            if (tid == 0) {
                atomicAdd(&g_cnt[grp], 1u);
                const unsigned target = 8u * (unsigned)(t + 1);
                while (*((volatile unsigned*)&g_cnt[grp]) < target) { }
            }
            __syncthreads();
            // reload full h for both batches from L2 (bypass L1)
            hs0[tid] = __ldcg(&g_hstate[b0 * HH + tid]);
            hs1[tid] = __ldcg(&g_hstate[b1 * HH + tid]);
            __syncthreads();
        }
    }
}

// ---------------- launch ----------------
extern "C" void kernel_launch(void* const* d_in, const int* in_sizes, int n_in,
                              void* d_out, int out_size)
{
    const float* x  = (const float*)d_in[0];   // [B,T,DIN]
    const float* Wx = (const float*)d_in[1];   // [DIN,4H]
    const float* Wh = (const float*)d_in[2];   // [H,4H]
    const float* b  = (const float*)d_in[3];   // [4H]
    const float* Wo = (const float*)d_in[4];   // [H,DOUT]
    const float* bo = (const float*)d_in[5];   // [DOUT]
    float* out = (float*)d_out;                // [B,T,DOUT]

    float *xg_ptr = nullptr, *hseq_ptr = nullptr;
    cudaGetSymbolAddress((void**)&xg_ptr, g_xg);
    cudaGetSymbolAddress((void**)&hseq_ptr, g_hseq);

    // reset sync counters (graph replays reuse state)
    init_kernel<<<1, 32>>>();

    // 1) xg = x @ Wx + b   : [131072,256] @ [256,1024]
    {
        dim3 grid(G4 / 128, (BB * TT) / 128);   // (8, 1024)
        sgemm_bias_128<<<grid, 256>>>(x, Wx, b, xg_ptr, BB * TT, G4, DIN);
    }

    // 2) recurrence over 4096 steps (persistent, 128 CTAs)
    lstm_rec<<<128, 256>>>(Wh);

    // 3) out = hseq @ Wo + bo : [131072,256] @ [256,256]
    {
        dim3 grid(256 / 128, (BB * TT) / 128);  // (2, 1024)
        sgemm_bias_128<<<grid, 256>>>(hseq_ptr, Wo, bo, out, BB * TT, 256, HH);
    }
}